// round 2
// baseline (speedup 1.0000x reference)
#include <cuda_runtime.h>
#include <cuda_bf16.h>

// Deformable conv2d, 1 channel, K=3, zero padding, torchvision bilinear rule.
// input : (B, 512, 512) f32
// weight: (1, 1, 3, 3)  f32
// offset: (B, 18, 512, 512) f32, layout [k*2+{y,x}][h][w]
// out   : (B, 512, 512) f32
//
// 4 pixels (consecutive w) per thread: offset planes read as float4,
// output written as float4. Input taps are scalar gathers (L1-resident).

#define HH 512
#define WW 512
#define HW (512 * 512)

__device__ __forceinline__ float bilin_sample(const float* __restrict__ inb,
                                              float y, float x)
{
    float y0f = floorf(y);
    float x0f = floorf(x);
    float ly = y - y0f;
    float lx = x - x0f;
    float hy = 1.0f - ly;
    float hx = 1.0f - lx;
    int y0 = (int)y0f;
    int x0 = (int)x0f;

    if (y0 >= 0 && y0 < (HH - 1) && x0 >= 0 && x0 < (WW - 1)) {
        // Fast path: whole 2x2 footprint in-bounds.
        const float* __restrict__ p = inb + y0 * WW + x0;
        float v00 = __ldg(p);
        float v01 = __ldg(p + 1);
        float v10 = __ldg(p + WW);
        float v11 = __ldg(p + WW + 1);
        return fmaf(hy, fmaf(hx, v00, lx * v01),
                    ly * fmaf(hx, v10, lx * v11));
    }
    // Slow path: per-corner zeroing, exactly as the reference.
    int y1 = y0 + 1;
    int x1 = x0 + 1;
    bool y0v = (y0 >= 0) && (y0 < HH);
    bool y1v = (y1 >= 0) && (y1 < HH);
    bool x0v = (x0 >= 0) && (x0 < WW);
    bool x1v = (x1 >= 0) && (x1 < WW);
    float v00 = (y0v && x0v) ? __ldg(&inb[y0 * WW + x0]) : 0.0f;
    float v01 = (y0v && x1v) ? __ldg(&inb[y0 * WW + x1]) : 0.0f;
    float v10 = (y1v && x0v) ? __ldg(&inb[y1 * WW + x0]) : 0.0f;
    float v11 = (y1v && x1v) ? __ldg(&inb[y1 * WW + x1]) : 0.0f;
    return fmaf(hy, fmaf(hx, v00, lx * v01),
                ly * fmaf(hx, v10, lx * v11));
}

__global__ __launch_bounds__(256) void DeformConv_90735479095316_kernel(
    const float* __restrict__ inp,
    const float* __restrict__ wgt,
    const float* __restrict__ off,
    float* __restrict__ out,
    int nquad)
{
    int q = blockIdx.x * blockDim.x + threadIdx.x;
    if (q >= nquad) return;

    int base = q << 2;               // first pixel of this quad
    int w = base & (WW - 1);         // w, w+1, w+2, w+3 (same row: 512 % 4 == 0)
    int h = (base >> 9) & (HH - 1);
    int b = base >> 18;

    const float* __restrict__ inb = inp + b * HW;
    const float4* __restrict__ offq =
        (const float4*)(off + (size_t)b * 18 * HW + h * WW + w);
    const int plane4 = HW / 4;       // float4 stride between offset planes

    float wk[9];
    #pragma unroll
    for (int k = 0; k < 9; k++) wk[k] = __ldg(&wgt[k]);

    float acc0 = 0.0f, acc1 = 0.0f, acc2 = 0.0f, acc3 = 0.0f;

    const float yb = (float)h;
    const float xb = (float)w;

    #pragma unroll
    for (int k = 0; k < 9; k++) {
        const float ky = (float)(k / 3 - 1);
        const float kx = (float)(k % 3 - 1);

        float4 oy = __ldg(&offq[(2 * k) * plane4]);
        float4 ox = __ldg(&offq[(2 * k + 1) * plane4]);

        float y  = yb + ky;
        float x0 = xb + kx;

        float s0 = bilin_sample(inb, y + oy.x, x0 + 0.0f + ox.x);
        float s1 = bilin_sample(inb, y + oy.y, x0 + 1.0f + ox.y);
        float s2 = bilin_sample(inb, y + oy.z, x0 + 2.0f + ox.z);
        float s3 = bilin_sample(inb, y + oy.w, x0 + 3.0f + ox.w);

        acc0 = fmaf(wk[k], s0, acc0);
        acc1 = fmaf(wk[k], s1, acc1);
        acc2 = fmaf(wk[k], s2, acc2);
        acc3 = fmaf(wk[k], s3, acc3);
    }

    float4 r;
    r.x = acc0; r.y = acc1; r.z = acc2; r.w = acc3;
    *((float4*)(out + base)) = r;
}

extern "C" void kernel_launch(void* const* d_in, const int* in_sizes, int n_in,
                              void* d_out, int out_size)
{
    const float* inp = (const float*)d_in[0];
    const float* wgt = (const float*)d_in[1];
    const float* off = (const float*)d_in[2];
    float* out = (float*)d_out;

    int nquad = out_size >> 2;       // B*H*W / 4
    int threads = 256;
    int blocks = (nquad + threads - 1) / threads;
    DeformConv_90735479095316_kernel<<<blocks, threads>>>(inp, wgt, off, out, nquad);
}